// round 1
// baseline (speedup 1.0000x reference)
#include <cuda_runtime.h>
#include <cstdint>

// EdgeConv fused kernel.
// out[b,n,o] = sum_c g[c]*W[o,c] + sum_c x[c]*(W[o,64+c]-W[o,c]) + bias[o]
// where g[c] = mean over the length-20 window [20c, 20c+20) of the flattened
// 20x64 neighbor-gather vector v (raw-reshape semantics of the reference).

#define BB 4
#define NN 32768
#define KK 20
#define CC 64          // channels
#define C2 128         // 2*C
#define OUTD 64
#define TP 64          // points per block tile
#define THREADS 256

__global__ __launch_bounds__(THREADS, 3)
void edgeconv_fused_kernel(const float* __restrict__ x,
                           const int* __restrict__ adj,
                           const float* __restrict__ W,
                           const float* __restrict__ bias,
                           float* __restrict__ out)
{
    __shared__ __align__(16) float sW[C2][OUTD];   // Wc^T: sW[cc][o]        32 KB
    __shared__ __align__(16) float sE[C2][TP + 1]; // E^T padded: sE[cc][p]  ~33 KB
    __shared__ float sS4[8][320];                  // per-warp 4-elem partial sums 10 KB
    __shared__ __align__(16) float sB[OUTD];

    const int tid = threadIdx.x;
    const int wid = tid >> 5;
    const int lid = tid & 31;
    const int tile = blockIdx.x;
    const int gp0 = tile * TP;

    // ---- Load combined weights Wc^T into smem ----
    // cc < 64  : Wc[o][cc] = W[o][cc]                (multiplies g)
    // cc >= 64 : Wc[o][cc] = W[o][cc] - W[o][cc-64]  (multiplies x)
    #pragma unroll
    for (int i = tid; i < C2 * OUTD; i += THREADS) {
        int cc = i >> 6;
        int o  = i & 63;
        float w = W[o * C2 + cc];
        if (cc >= CC) w -= W[o * C2 + (cc - CC)];
        sW[cc][o] = w;
    }
    if (tid < OUTD) sB[tid] = bias[tid];

    // ---- Gather + window-mean phase: warp 'wid' handles points wid*8 .. wid*8+7 ----
    #pragma unroll 1
    for (int pi = 0; pi < 8; ++pi) {
        const int p  = wid * 8 + pi;
        const int gp = gp0 + p;
        const int b  = gp >> 15;       // N = 32768
        const int n  = gp & (NN - 1);

        const float2* __restrict__ xb = (const float2*)(x + (size_t)b * NN * CC);

        // adj row (20 ints); lane j holds adj[j]
        int a = 0;
        if (lid < KK) a = adj[(size_t)gp * KK + lid];

        // Gather 20 neighbor rows; build s4[q] = v[4q]+v[4q+1]+v[4q+2]+v[4q+3]
        #pragma unroll
        for (int j = 0; j < KK; ++j) {
            int nbr = __shfl_sync(0xffffffffu, a, j);
            float2 v = xb[nbr * 32 + lid];       // coalesced 256B row
            float pair = v.x + v.y;              // v[64j+2l] + v[64j+2l+1]
            float s4 = pair + __shfl_xor_sync(0xffffffffu, pair, 1);
            if ((lid & 1) == 0)
                sS4[wid][j * 16 + (lid >> 1)] = s4;   // conflict-free (16 banks)
        }
        __syncwarp();

        // g[2l] = sum s4[10l..10l+4], g[2l+1] = sum s4[10l+5..10l+9]
        float acc0 = 0.0f, acc1 = 0.0f;
        #pragma unroll
        for (int t = 0; t < 5; ++t)  acc0 += sS4[wid][10 * lid + t];
        #pragma unroll
        for (int t = 5; t < 10; ++t) acc1 += sS4[wid][10 * lid + t];

        const float inv = 1.0f / (float)KK;
        float2 xv = xb[n * 32 + lid];

        sE[2 * lid][p]      = acc0 * inv;   // g part
        sE[2 * lid + 1][p]  = acc1 * inv;
        sE[CC + 2 * lid][p] = xv.x;         // x part
        sE[CC + 2 * lid + 1][p] = xv.y;

        __syncwarp();  // protect sS4 WAR before next point
    }

    __syncthreads();

    // ---- GEMM phase: 16x16 threads, 4x4 register micro-tiles ----
    // thread (ty,tx): points 4*ty..4*ty+3, outputs 4*tx..4*tx+3
    const int tx = tid & 15;
    const int ty = tid >> 4;

    float acc[4][4];
    #pragma unroll
    for (int i = 0; i < 4; ++i)
        #pragma unroll
        for (int j = 0; j < 4; ++j) acc[i][j] = 0.0f;

    #pragma unroll 4
    for (int cc = 0; cc < C2; ++cc) {
        float e0 = sE[cc][4 * ty + 0];   // broadcast loads
        float e1 = sE[cc][4 * ty + 1];
        float e2 = sE[cc][4 * ty + 2];
        float e3 = sE[cc][4 * ty + 3];
        float4 w = *(const float4*)&sW[cc][4 * tx];

        acc[0][0] += e0 * w.x; acc[0][1] += e0 * w.y; acc[0][2] += e0 * w.z; acc[0][3] += e0 * w.w;
        acc[1][0] += e1 * w.x; acc[1][1] += e1 * w.y; acc[1][2] += e1 * w.z; acc[1][3] += e1 * w.w;
        acc[2][0] += e2 * w.x; acc[2][1] += e2 * w.y; acc[2][2] += e2 * w.z; acc[2][3] += e2 * w.w;
        acc[3][0] += e3 * w.x; acc[3][1] += e3 * w.y; acc[3][2] += e3 * w.z; acc[3][3] += e3 * w.w;
    }

    // ---- Epilogue: add bias, write out ----
    float4 bb = *(const float4*)&sB[4 * tx];
    #pragma unroll
    for (int i = 0; i < 4; ++i) {
        float4 r;
        r.x = acc[i][0] + bb.x;
        r.y = acc[i][1] + bb.y;
        r.z = acc[i][2] + bb.z;
        r.w = acc[i][3] + bb.w;
        *(float4*)&out[(size_t)(gp0 + 4 * ty + i) * OUTD + 4 * tx] = r;
    }
}

extern "C" void kernel_launch(void* const* d_in, const int* in_sizes, int n_in,
                              void* d_out, int out_size)
{
    (void)in_sizes; (void)n_in; (void)out_size;
    const float* x    = (const float*)d_in[0];
    const int*   adj  = (const int*)d_in[1];
    const float* W    = (const float*)d_in[2];
    const float* bias = (const float*)d_in[3];
    float* out = (float*)d_out;

    const int tiles = (BB * NN) / TP;  // 2048
    edgeconv_fused_kernel<<<tiles, THREADS>>>(x, adj, W, bias, out);
}

// round 2
// speedup vs baseline: 2.0308x; 2.0308x over previous
#include <cuda_runtime.h>
#include <cstdint>

// EdgeConv fused kernel, round 2.
// out[b,n,o] = sum_cc E[cc]*Wc[o][cc] + bias[o]
//   E = [g | x], g[c] = mean over window [20c,20c+20) of flattened 20x64 gather,
//   Wc[o][c] = W[o][c], Wc[o][64+c] = W[o][64+c] - W[o][c].

#define BB 4
#define NN 32768
#define KK 20
#define CC 64
#define C2 128
#define OUTD 64
#define TP 64
#define THREADS 256
#define SE_STRIDE 132   // floats; keeps 16B alignment, breaks bank aliasing for e-reads

__device__ __forceinline__ unsigned long long ffma2(unsigned long long a,
                                                    unsigned long long b,
                                                    unsigned long long c)
{
    unsigned long long d;
    asm("fma.rn.f32x2 %0, %1, %2, %3;" : "=l"(d) : "l"(a), "l"(b), "l"(c));
    return d;
}

__device__ __forceinline__ float f2lo(unsigned long long v) {
    return __uint_as_float((unsigned)(v & 0xffffffffu));
}
__device__ __forceinline__ float f2hi(unsigned long long v) {
    return __uint_as_float((unsigned)(v >> 32));
}

__global__ __launch_bounds__(THREADS, 3)
void edgeconv_fused_kernel(const float* __restrict__ x,
                           const int* __restrict__ adj,
                           const float* __restrict__ W,
                           const float* __restrict__ bias,
                           float* __restrict__ out)
{
    __shared__ __align__(16) float sW[OUTD * C2];        // swizzled Wc[o][cc]  32 KB
    __shared__ __align__(16) float sE[TP * SE_STRIDE];   // E[p][cc]            33 KB
    __shared__ __align__(16) float sS4[8][320];          // per-warp s4 scratch 10 KB
    __shared__ __align__(16) float sB[OUTD];

    const int tid = threadIdx.x;
    const int wid = tid >> 5;
    const int lid = tid & 31;
    const int gp0 = blockIdx.x * TP;
    const int b   = gp0 >> 15;            // N = 32768, tiles never straddle batches
    const int n0  = gp0 & (NN - 1);

    // ---- Combined weights, stored with 16B-chunk XOR swizzle ----
    // physical float idx = o*128 + ((cc4 ^ ((o>>2)&7))<<2) + (cc&3)
    #pragma unroll
    for (int i = tid; i < OUTD * C2; i += THREADS) {
        int o  = i >> 7;
        int cc = i & 127;
        float w = W[o * C2 + cc];
        if (cc >= CC) w -= W[o * C2 + (cc - CC)];
        int phys = (o << 7) + ((((cc >> 2) ^ ((o >> 2) & 7)) << 2) | (cc & 3));
        sW[phys] = w;
    }
    if (tid < OUTD) sB[tid] = bias[tid];

    // ---- Gather + window-mean: warp wid handles points wid*8 .. wid*8+7 ----
    const float4* __restrict__ xb4 = (const float4*)(x + (size_t)b * NN * CC);
    const float2* __restrict__ xb2 = (const float2*)(x + (size_t)b * NN * CC);
    float* __restrict__ sS4w = &sS4[wid][0];

    // prefetch adj rows for all 8 points (lane j<20 holds adj[...,j])
    int a[8];
    #pragma unroll
    for (int pi = 0; pi < 8; ++pi) {
        int gp = gp0 + wid * 8 + pi;
        a[pi] = (lid < KK) ? adj[(size_t)gp * KK + lid] : 0;
    }

    const int q  = lid & 15;
    const int hh = lid >> 4;      // half-warp: 0 -> even row, 1 -> odd row
    const float inv = 1.0f / (float)KK;

    #pragma unroll
    for (int pi = 0; pi < 8; ++pi) {
        const int p = wid * 8 + pi;
        const int n = n0 + p;

        // 10 iterations: rows 2i (lanes 0-15) and 2i+1 (lanes 16-31)
        #pragma unroll
        for (int i = 0; i < 10; ++i) {
            int r   = 2 * i + hh;
            int nbr = __shfl_sync(0xffffffffu, a[pi], r);
            float4 v = xb4[nbr * 16 + q];
            float s  = (v.x + v.y) + (v.z + v.w);
            sS4w[32 * i + lid] = s;          // conflict-free (consecutive)
        }
        __syncwarp();

        // g[2l] = sum s4[10l..10l+4], g[2l+1] = sum s4[10l+5..10l+9]
        float2 r0 = *(const float2*)&sS4w[10 * lid + 0];
        float2 r1 = *(const float2*)&sS4w[10 * lid + 2];
        float2 r2 = *(const float2*)&sS4w[10 * lid + 4];
        float2 r3 = *(const float2*)&sS4w[10 * lid + 6];
        float2 r4 = *(const float2*)&sS4w[10 * lid + 8];
        float acc0 = ((r0.x + r0.y) + (r1.x + r1.y)) + r2.x;
        float acc1 = (r2.y + (r3.x + r3.y)) + (r4.x + r4.y);

        float2 xv = xb2[n * 32 + lid];

        float2 g2; g2.x = acc0 * inv; g2.y = acc1 * inv;
        *(float2*)&sE[p * SE_STRIDE + 2 * lid]      = g2;   // coalesced, conflict-free
        float2 xw; xw.x = xv.x; xw.y = xv.y;
        *(float2*)&sE[p * SE_STRIDE + CC + 2 * lid] = xw;

        __syncwarp();   // protect sS4 WAR before next point
    }

    __syncthreads();

    // ---- GEMM: 16x16 threads, 4 points x 4 outs per thread, f32x2 packed over cc ----
    const int tx  = tid & 15;
    const int ty  = tid >> 4;
    const int swz = tx & 7;

    unsigned long long acc[4][4];
    #pragma unroll
    for (int i = 0; i < 4; ++i)
        #pragma unroll
        for (int j = 0; j < 4; ++j) acc[i][j] = 0ULL;

    const float* eBase = &sE[(4 * ty) * SE_STRIDE];
    const float* wBase = &sW[(4 * tx) << 7];

    #pragma unroll 1
    for (int it = 0; it < 32; ++it) {      // 4 cc per iteration
        int eo = it << 2;
        ulonglong2 e0 = *(const ulonglong2*)(eBase + 0 * SE_STRIDE + eo);
        ulonglong2 e1 = *(const ulonglong2*)(eBase + 1 * SE_STRIDE + eo);
        ulonglong2 e2 = *(const ulonglong2*)(eBase + 2 * SE_STRIDE + eo);
        ulonglong2 e3 = *(const ulonglong2*)(eBase + 3 * SE_STRIDE + eo);
        int wo = (it ^ swz) << 2;
        ulonglong2 w0 = *(const ulonglong2*)(wBase + (0 << 7) + wo);
        ulonglong2 w1 = *(const ulonglong2*)(wBase + (1 << 7) + wo);
        ulonglong2 w2 = *(const ulonglong2*)(wBase + (2 << 7) + wo);
        ulonglong2 w3 = *(const ulonglong2*)(wBase + (3 << 7) + wo);

        acc[0][0] = ffma2(e0.x, w0.x, acc[0][0]); acc[0][0] = ffma2(e0.y, w0.y, acc[0][0]);
        acc[0][1] = ffma2(e0.x, w1.x, acc[0][1]); acc[0][1] = ffma2(e0.y, w1.y, acc[0][1]);
        acc[0][2] = ffma2(e0.x, w2.x, acc[0][2]); acc[0][2] = ffma2(e0.y, w2.y, acc[0][2]);
        acc[0][3] = ffma2(e0.x, w3.x, acc[0][3]); acc[0][3] = ffma2(e0.y, w3.y, acc[0][3]);

        acc[1][0] = ffma2(e1.x, w0.x, acc[1][0]); acc[1][0] = ffma2(e1.y, w0.y, acc[1][0]);
        acc[1][1] = ffma2(e1.x, w1.x, acc[1][1]); acc[1][1] = ffma2(e1.y, w1.y, acc[1][1]);
        acc[1][2] = ffma2(e1.x, w2.x, acc[1][2]); acc[1][2] = ffma2(e1.y, w2.y, acc[1][2]);
        acc[1][3] = ffma2(e1.x, w3.x, acc[1][3]); acc[1][3] = ffma2(e1.y, w3.y, acc[1][3]);

        acc[2][0] = ffma2(e2.x, w0.x, acc[2][0]); acc[2][0] = ffma2(e2.y, w0.y, acc[2][0]);
        acc[2][1] = ffma2(e2.x, w1.x, acc[2][1]); acc[2][1] = ffma2(e2.y, w1.y, acc[2][1]);
        acc[2][2] = ffma2(e2.x, w2.x, acc[2][2]); acc[2][2] = ffma2(e2.y, w2.y, acc[2][2]);
        acc[2][3] = ffma2(e2.x, w3.x, acc[2][3]); acc[2][3] = ffma2(e2.y, w3.y, acc[2][3]);

        acc[3][0] = ffma2(e3.x, w0.x, acc[3][0]); acc[3][0] = ffma2(e3.y, w0.y, acc[3][0]);
        acc[3][1] = ffma2(e3.x, w1.x, acc[3][1]); acc[3][1] = ffma2(e3.y, w1.y, acc[3][1]);
        acc[3][2] = ffma2(e3.x, w2.x, acc[3][2]); acc[3][2] = ffma2(e3.y, w2.y, acc[3][2]);
        acc[3][3] = ffma2(e3.x, w3.x, acc[3][3]); acc[3][3] = ffma2(e3.y, w3.y, acc[3][3]);
    }

    // ---- Epilogue ----
    float4 bb = *(const float4*)&sB[4 * tx];
    #pragma unroll
    for (int i = 0; i < 4; ++i) {
        float4 r;
        r.x = (f2lo(acc[i][0]) + f2hi(acc[i][0])) + bb.x;
        r.y = (f2lo(acc[i][1]) + f2hi(acc[i][1])) + bb.y;
        r.z = (f2lo(acc[i][2]) + f2hi(acc[i][2])) + bb.z;
        r.w = (f2lo(acc[i][3]) + f2hi(acc[i][3])) + bb.w;
        *(float4*)&out[(size_t)(gp0 + 4 * ty + i) * OUTD + 4 * tx] = r;
    }
}

extern "C" void kernel_launch(void* const* d_in, const int* in_sizes, int n_in,
                              void* d_out, int out_size)
{
    (void)in_sizes; (void)n_in; (void)out_size;
    const float* x    = (const float*)d_in[0];
    const int*   adj  = (const int*)d_in[1];
    const float* W    = (const float*)d_in[2];
    const float* bias = (const float*)d_in[3];
    float* out = (float*)d_out;

    const int tiles = (BB * NN) / TP;   // 2048
    edgeconv_fused_kernel<<<tiles, THREADS>>>(x, adj, W, bias, out);
}